// round 4
// baseline (speedup 1.0000x reference)
#include <cuda_runtime.h>
#include <cuda_fp16.h>
#include <math.h>

#define NN 100000
#define EE 1600000
#define NCAND 10000
#define GG 1000
#define ND 32
#define ED 8
#define LL 4

__device__ float g_h[NN * ND];                        // 12.8 MB fp32
__device__ __align__(16) __half g_hs[NN * ED];        // 1.6 MB fp16
__device__ __align__(16) __half g_hd[NN * ED];        // 1.6 MB fp16
__device__ __align__(16) float  g_agg[NN * ED];       // 3.2 MB fp32
__device__ __align__(16) __half g_e[(size_t)EE * ED]; // 25.6 MB fp16

#define R_A (NN * ND)              // h init
#define R_B (R_A + NN * 16)        // hs/hd layer 0
#define R_C (R_B + EE)             // e init
#define R_D (R_C + NN * ED)        // agg zero
#define TOT R_D

// Fused init: h, layer-0 hs/hd (folded 2x16), e (fp16), agg zero.
__global__ void k_init(const float* __restrict__ x,
                       const float* __restrict__ Wn,
                       const float* __restrict__ bn,
                       const float* __restrict__ ea,
                       const float* __restrict__ Wei,
                       const float* __restrict__ bei,
                       const float* __restrict__ Wel,
                       const float* __restrict__ bel) {
    __shared__ float sC[2][16];
    __shared__ float sc0[16];
    int tid = threadIdx.x;
    if (tid < 48) {
        int r = tid >> 4, j = tid & 15;
        float acc = 0.f;
        if (r < 2) {
            for (int i = 0; i < ND; i++) {
                float w = (j < 8) ? Wel[i * ED + j] : Wel[(ND + i) * ED + (j - 8)];
                acc = fmaf(Wn[r * ND + i], w, acc);
            }
            sC[r][j] = acc;
        } else {
            for (int i = 0; i < ND; i++) {
                float w = (j < 8) ? Wel[i * ED + j] : Wel[(ND + i) * ED + (j - 8)];
                acc = fmaf(bn[i], w, acc);
            }
            sc0[j] = acc + ((j < 8) ? bel[j] : 0.f);
        }
    }
    __syncthreads();
    long t = (long)blockIdx.x * blockDim.x + tid;
    if (t < R_A) {
        int n = (int)(t >> 5), c = (int)(t & 31);
        g_h[t] = fmaf(x[2 * n], Wn[c], fmaf(x[2 * n + 1], Wn[ND + c], bn[c]));
    } else if (t < R_B) {
        long u = t - R_A;
        int n = (int)(u >> 4), j = (int)(u & 15);
        float v = fmaf(x[2 * n], sC[0][j], fmaf(x[2 * n + 1], sC[1][j], sc0[j]));
        if (j < 8) g_hs[n * ED + j] = __float2half(v);
        else       g_hd[n * ED + (j - 8)] = __float2half(v);
    } else if (t < R_C) {
        long e = t - R_B;
        float v = ea[e];
        __half2 h4[4];
#pragma unroll
        for (int k = 0; k < 4; k++)
            h4[k] = __floats2half2_rn(fmaf(v, Wei[2 * k], bei[2 * k]),
                                      fmaf(v, Wei[2 * k + 1], bei[2 * k + 1]));
        ((uint4*)g_e)[e] = *(uint4*)h4;
    } else if (t < R_D) {
        g_agg[t - R_C] = 0.f;
    }
}

__device__ __forceinline__ void edge_one(int e, int src, int dst,
                                         const float* sW) {
    uint4 ev = __ldcs((const uint4*)&g_e[(size_t)e * ED]);
    uint4 sv = *(const uint4*)&g_hs[(size_t)src * ED];
    uint4 dv = *(const uint4*)&g_hd[(size_t)dst * ED];
    const __half2* eh = (const __half2*)&ev;
    const __half2* sh = (const __half2*)&sv;
    const __half2* dh = (const __half2*)&dv;
    float ein[8], base[8];
#pragma unroll
    for (int k = 0; k < 4; k++) {
        float2 ef = __half22float2(eh[k]);
        float2 sf = __half22float2(sh[k]);
        float2 df = __half22float2(dh[k]);
        ein[2 * k] = ef.x;  ein[2 * k + 1] = ef.y;
        base[2 * k] = sf.x + df.x;
        base[2 * k + 1] = sf.y + df.y;
    }
    float ne[8];
#pragma unroll
    for (int j = 0; j < 8; j++) {
        float acc = base[j];
#pragma unroll
        for (int i = 0; i < 8; i++) acc = fmaf(ein[i], sW[i * ED + j], acc);
        ne[j] = fmaxf(acc, 0.f);
    }
    float* ap = &g_agg[(size_t)dst * ED];
    asm volatile("red.global.add.v4.f32 [%0], {%1,%2,%3,%4};"
                 :: "l"(ap), "f"(ne[0]), "f"(ne[1]), "f"(ne[2]), "f"(ne[3]) : "memory");
    asm volatile("red.global.add.v4.f32 [%0], {%1,%2,%3,%4};"
                 :: "l"(ap + 4), "f"(ne[4]), "f"(ne[5]), "f"(ne[6]), "f"(ne[7]) : "memory");
    __half2 out[4];
#pragma unroll
    for (int k = 0; k < 4; k++)
        out[k] = __floats2half2_rn(ein[2 * k] + ne[2 * k], ein[2 * k + 1] + ne[2 * k + 1]);
    __stcs((uint4*)&g_e[(size_t)e * ED], *(uint4*)out);
}

// Two edges per thread for ILP; streaming hints on e.
__global__ void k_edge(const int* __restrict__ ei,
                       const float* __restrict__ Wel, int l) {
    __shared__ float sW[ED * ED];
    if (threadIdx.x < ED * ED)
        sW[threadIdx.x] = Wel[l * (2 * ND + ED) * ED + 2 * ND * ED + threadIdx.x];
    __syncthreads();
    int t = blockIdx.x * blockDim.x + threadIdx.x;
    int e0 = t * 2;
    if (e0 >= EE) return;
    int2 srcs = *(const int2*)(ei + e0);
    int2 dsts = *(const int2*)(ei + EE + e0);
    edge_one(e0,     srcs.x, dsts.x, sW);
    edge_one(e0 + 1, srcs.y, dsts.y, sW);
}

// Warp per node: node MLP + residual; epilogue precomputes next layer hs/hd,
// re-zeros agg.
__global__ void k_node(const float* __restrict__ Wnl,
                       const float* __restrict__ bnl,
                       const float* __restrict__ Wel,
                       const float* __restrict__ bel, int l) {
    __shared__ float sW[(ND + ED) * ND];
    __shared__ float sb[ND];
    __shared__ float sE[ND][16];
    __shared__ float sbe[8];
    const int last = (l == LL - 1);
    for (int i = threadIdx.x; i < (ND + ED) * ND; i += blockDim.x)
        sW[i] = Wnl[l * (ND + ED) * ND + i];
    if (threadIdx.x < ND) sb[threadIdx.x] = bnl[l * ND + threadIdx.x];
    if (!last) {
        const float* W = Wel + (l + 1) * (2 * ND + ED) * ED;
        for (int i = threadIdx.x; i < ND * 16; i += blockDim.x) {
            int r = i >> 4, j = i & 15;
            sE[r][j] = (j < 8) ? W[r * ED + j] : W[(ND + r) * ED + (j - 8)];
        }
        if (threadIdx.x < 8) sbe[threadIdx.x] = bel[(l + 1) * ED + threadIdx.x];
    }
    __syncthreads();
    int warp = (blockIdx.x * blockDim.x + threadIdx.x) >> 5;
    int lane = threadIdx.x & 31;
    if (warp >= NN) return;
    float hv = g_h[warp * ND + lane];
    float av = (lane < ED) ? g_agg[warp * ED + lane] : 0.f;
    float r = sb[lane];
#pragma unroll
    for (int i = 0; i < ND; i++)
        r = fmaf(__shfl_sync(0xffffffffu, hv, i), sW[i * ND + lane], r);
#pragma unroll
    for (int i = 0; i < ED; i++)
        r = fmaf(__shfl_sync(0xffffffffu, av, i), sW[(ND + i) * ND + lane], r);
    float hnew = hv + fmaxf(r, 0.f);
    g_h[warp * ND + lane] = hnew;
    if (!last) {
        float acc = (lane < 8) ? sbe[lane] : 0.f;
        int jj = lane & 15;
#pragma unroll
        for (int i = 0; i < ND; i++)
            acc = fmaf(__shfl_sync(0xffffffffu, hnew, i), sE[i][jj], acc);
        if (lane < 8) {
            g_hs[warp * ED + lane] = __float2half(acc);
            g_agg[warp * ED + lane] = 0.f;
        } else if (lane < 16) {
            g_hd[warp * ED + (lane - 8)] = __float2half(acc);
        }
    }
}

// ---------------- fused single-block readout ----------------

__device__ __forceinline__ unsigned enc_f(float f) {
    unsigned u = __float_as_uint(f);
    return (u & 0x80000000u) ? ~u : (u | 0x80000000u);
}
__device__ __forceinline__ float dec_f(unsigned k) {
    return __uint_as_float((k & 0x80000000u) ? (k ^ 0x80000000u) : ~k);
}

#define RITER ((NCAND + 1023) / 1024)

__global__ void k_readout(const int* __restrict__ cand,
                          const int* __restrict__ batch,
                          const float* __restrict__ Wout,
                          const float* __restrict__ bout,
                          float* __restrict__ out) {
    __shared__ unsigned smx[GG];
    __shared__ float ssum[GG];
    int tid = threadIdx.x;
    for (int i = tid; i < GG; i += 1024) { smx[i] = 0u; ssum[i] = 0.f; }
    __syncthreads();
    float lg[RITER];
    int sg[RITER];
#pragma unroll
    for (int k = 0; k < RITER; k++) {
        int c = k * 1024 + tid;
        if (c < NCAND) {
            int n = cand[c];
            float acc = bout[0];
            const float* hrow = &g_h[n * ND];
#pragma unroll
            for (int i = 0; i < ND; i++) acc = fmaf(hrow[i], Wout[i], acc);
            lg[k] = acc;
            sg[k] = batch[n];
            atomicMax(&smx[sg[k]], enc_f(acc));
        }
    }
    __syncthreads();
#pragma unroll
    for (int k = 0; k < RITER; k++) {
        int c = k * 1024 + tid;
        if (c < NCAND) {
            lg[k] -= dec_f(smx[sg[k]]);
            atomicAdd(&ssum[sg[k]], expf(lg[k]));
        }
    }
    __syncthreads();
#pragma unroll
    for (int k = 0; k < RITER; k++) {
        int c = k * 1024 + tid;
        if (c < NCAND) out[c] = lg[k] - logf(ssum[sg[k]]);
    }
}

extern "C" void kernel_launch(void* const* d_in, const int* in_sizes, int n_in,
                              void* d_out, int out_size) {
    const float* x         = (const float*)d_in[0];
    const float* edge_attr = (const float*)d_in[1];
    const float* Wn_in     = (const float*)d_in[2];
    const float* bn_in     = (const float*)d_in[3];
    const float* We_in     = (const float*)d_in[4];
    const float* be_in     = (const float*)d_in[5];
    const float* We_l      = (const float*)d_in[6];
    const float* be_l      = (const float*)d_in[7];
    const float* Wn_l      = (const float*)d_in[8];
    const float* bn_l      = (const float*)d_in[9];
    const float* Wout      = (const float*)d_in[10];
    const float* bout      = (const float*)d_in[11];
    const int* edge_index  = (const int*)d_in[12];
    const int* batch       = (const int*)d_in[13];
    const int* cand        = (const int*)d_in[14];
    float* out = (float*)d_out;

    k_init<<<(TOT + 255) / 256, 256>>>(x, Wn_in, bn_in, edge_attr, We_in, be_in,
                                       We_l, be_l);
    for (int l = 0; l < LL; l++) {
        k_edge<<<(EE / 2 + 255) / 256, 256>>>(edge_index, We_l, l);
        k_node<<<(NN * 32 + 255) / 256, 256>>>(Wn_l, bn_l, We_l, be_l, l);
    }
    k_readout<<<1, 1024>>>(cand, batch, Wout, bout, out);
}

// round 5
// speedup vs baseline: 1.4273x; 1.4273x over previous
#include <cuda_runtime.h>
#include <cuda_fp16.h>
#include <math.h>

#define NN 100000
#define EE 1600000
#define NCAND 10000
#define GG 1000
#define ND 32
#define ED 8
#define LL 4

__device__ float g_h[NN * ND];                        // 12.8 MB fp32
__device__ __align__(16) __half g_hs[NN * ED];        // 1.6 MB fp16
__device__ __align__(16) __half g_hd[NN * ED];        // 1.6 MB fp16
__device__ __align__(16) float  g_agg[NN * ED];       // 3.2 MB fp32
__device__ __align__(16) __half g_e[(size_t)EE * ED]; // 25.6 MB fp16
__device__ float g_nl[NN];                            // per-node logits

#define R_A (NN * ND)              // h init
#define R_B (R_A + NN * 16)        // hs/hd layer 0
#define R_C (R_B + NN * ED)        // agg zero
#define TOT R_C

// Fused init: h, layer-0 hs/hd (folded 2x16 matrix), agg zero. (No e init —
// layer-0 e is computed in-register inside k_edge from the scalar ea.)
__global__ void k_init(const float* __restrict__ x,
                       const float* __restrict__ Wn,
                       const float* __restrict__ bn,
                       const float* __restrict__ Wel,
                       const float* __restrict__ bel) {
    __shared__ float sC[2][16];
    __shared__ float sc0[16];
    int tid = threadIdx.x;
    if (tid < 48) {
        int r = tid >> 4, j = tid & 15;
        float acc = 0.f;
        if (r < 2) {
            for (int i = 0; i < ND; i++) {
                float w = (j < 8) ? Wel[i * ED + j] : Wel[(ND + i) * ED + (j - 8)];
                acc = fmaf(Wn[r * ND + i], w, acc);
            }
            sC[r][j] = acc;
        } else {
            for (int i = 0; i < ND; i++) {
                float w = (j < 8) ? Wel[i * ED + j] : Wel[(ND + i) * ED + (j - 8)];
                acc = fmaf(bn[i], w, acc);
            }
            sc0[j] = acc + ((j < 8) ? bel[j] : 0.f);
        }
    }
    __syncthreads();
    long t = (long)blockIdx.x * blockDim.x + tid;
    if (t < R_A) {
        int n = (int)(t >> 5), c = (int)(t & 31);
        g_h[t] = fmaf(x[2 * n], Wn[c], fmaf(x[2 * n + 1], Wn[ND + c], bn[c]));
    } else if (t < R_B) {
        long u = t - R_A;
        int n = (int)(u >> 4), j = (int)(u & 15);
        float v = fmaf(x[2 * n], sC[0][j], fmaf(x[2 * n + 1], sC[1][j], sc0[j]));
        if (j < 8) g_hs[n * ED + j] = __float2half(v);
        else       g_hd[n * ED + (j - 8)] = __float2half(v);
    } else if (t < R_C) {
        g_agg[t - R_B] = 0.f;
    }
}

// One edge per thread (occupancy is what hides L2 latency here — keep regs low).
// l==0: e computed in-register from scalar ea (rank-1). l<LL-1: write e+ne back.
__global__ void k_edge(const int* __restrict__ ei,
                       const float* __restrict__ ea,
                       const float* __restrict__ Wel,
                       const float* __restrict__ Wei,
                       const float* __restrict__ bei, int l) {
    __shared__ float sW[ED * ED];
    __shared__ float sWei[ED], sbei[ED];
    if (threadIdx.x < ED * ED)
        sW[threadIdx.x] = Wel[l * (2 * ND + ED) * ED + 2 * ND * ED + threadIdx.x];
    if (l == 0 && threadIdx.x >= 64 && threadIdx.x < 64 + ED) {
        sWei[threadIdx.x - 64] = Wei[threadIdx.x - 64];
        sbei[threadIdx.x - 64] = bei[threadIdx.x - 64];
    }
    __syncthreads();
    int e = blockIdx.x * blockDim.x + threadIdx.x;
    if (e >= EE) return;
    int src = ei[e], dst = ei[EE + e];
    float ein[8];
    if (l == 0) {
        float v = ea[e];
#pragma unroll
        for (int j = 0; j < 8; j++) ein[j] = fmaf(v, sWei[j], sbei[j]);
    } else {
        uint4 ev = *(const uint4*)&g_e[(size_t)e * ED];
        const __half2* eh = (const __half2*)&ev;
#pragma unroll
        for (int k = 0; k < 4; k++) {
            float2 ef = __half22float2(eh[k]);
            ein[2 * k] = ef.x;
            ein[2 * k + 1] = ef.y;
        }
    }
    uint4 sv = *(const uint4*)&g_hs[(size_t)src * ED];
    uint4 dv = *(const uint4*)&g_hd[(size_t)dst * ED];
    const __half2* sh = (const __half2*)&sv;
    const __half2* dh = (const __half2*)&dv;
    float base[8];
#pragma unroll
    for (int k = 0; k < 4; k++) {
        float2 sf = __half22float2(sh[k]);
        float2 df = __half22float2(dh[k]);
        base[2 * k] = sf.x + df.x;
        base[2 * k + 1] = sf.y + df.y;
    }
    float ne[8];
#pragma unroll
    for (int j = 0; j < 8; j++) {
        float acc = base[j];
#pragma unroll
        for (int i = 0; i < 8; i++) acc = fmaf(ein[i], sW[i * ED + j], acc);
        ne[j] = fmaxf(acc, 0.f);
    }
    float* ap = &g_agg[(size_t)dst * ED];
    asm volatile("red.global.add.v4.f32 [%0], {%1,%2,%3,%4};"
                 :: "l"(ap), "f"(ne[0]), "f"(ne[1]), "f"(ne[2]), "f"(ne[3]) : "memory");
    asm volatile("red.global.add.v4.f32 [%0], {%1,%2,%3,%4};"
                 :: "l"(ap + 4), "f"(ne[4]), "f"(ne[5]), "f"(ne[6]), "f"(ne[7]) : "memory");
    if (l < LL - 1) {
        __half2 out[4];
#pragma unroll
        for (int k = 0; k < 4; k++)
            out[k] = __floats2half2_rn(ein[2 * k] + ne[2 * k], ein[2 * k + 1] + ne[2 * k + 1]);
        ((uint4*)&g_e[(size_t)e * ED])[0] = *(uint4*)out;
    }
}

// Warp per node: node MLP + residual.
// l < LL-1: epilogue precomputes next layer hs/hd, re-zeros agg.
// l == LL-1: epilogue computes per-node logit h_new . Wout + bout.
__global__ void k_node(const float* __restrict__ Wnl,
                       const float* __restrict__ bnl,
                       const float* __restrict__ Wel,
                       const float* __restrict__ bel,
                       const float* __restrict__ Wout,
                       const float* __restrict__ bout, int l) {
    __shared__ float sW[(ND + ED) * ND];
    __shared__ float sb[ND];
    __shared__ float sE[ND][16];
    __shared__ float sbe[8];
    __shared__ float sWo[ND];
    __shared__ float sbo;
    const int last = (l == LL - 1);
    for (int i = threadIdx.x; i < (ND + ED) * ND; i += blockDim.x)
        sW[i] = Wnl[l * (ND + ED) * ND + i];
    if (threadIdx.x < ND) sb[threadIdx.x] = bnl[l * ND + threadIdx.x];
    if (!last) {
        const float* W = Wel + (l + 1) * (2 * ND + ED) * ED;
        for (int i = threadIdx.x; i < ND * 16; i += blockDim.x) {
            int r = i >> 4, j = i & 15;
            sE[r][j] = (j < 8) ? W[r * ED + j] : W[(ND + r) * ED + (j - 8)];
        }
        if (threadIdx.x < 8) sbe[threadIdx.x] = bel[(l + 1) * ED + threadIdx.x];
    } else {
        if (threadIdx.x < ND) sWo[threadIdx.x] = Wout[threadIdx.x];
        if (threadIdx.x == 0) sbo = bout[0];
    }
    __syncthreads();
    int warp = (blockIdx.x * blockDim.x + threadIdx.x) >> 5;
    int lane = threadIdx.x & 31;
    if (warp >= NN) return;
    float hv = g_h[warp * ND + lane];
    float av = (lane < ED) ? g_agg[warp * ED + lane] : 0.f;
    float r = sb[lane];
#pragma unroll
    for (int i = 0; i < ND; i++)
        r = fmaf(__shfl_sync(0xffffffffu, hv, i), sW[i * ND + lane], r);
#pragma unroll
    for (int i = 0; i < ED; i++)
        r = fmaf(__shfl_sync(0xffffffffu, av, i), sW[(ND + i) * ND + lane], r);
    float hnew = hv + fmaxf(r, 0.f);
    if (!last) {
        g_h[warp * ND + lane] = hnew;
        float acc = (lane < 8) ? sbe[lane] : 0.f;
        int jj = lane & 15;
#pragma unroll
        for (int i = 0; i < ND; i++)
            acc = fmaf(__shfl_sync(0xffffffffu, hnew, i), sE[i][jj], acc);
        if (lane < 8) {
            g_hs[warp * ED + lane] = __float2half(acc);
            g_agg[warp * ED + lane] = 0.f;
        } else if (lane < 16) {
            g_hd[warp * ED + (lane - 8)] = __float2half(acc);
        }
    } else {
        float p = hnew * sWo[lane];
#pragma unroll
        for (int s = 16; s > 0; s >>= 1)
            p += __shfl_xor_sync(0xffffffffu, p, s);
        if (lane == 0) g_nl[warp] = p + sbo;
    }
}

// ---------------- fused single-block readout over precomputed node logits ----

__device__ __forceinline__ unsigned enc_f(float f) {
    unsigned u = __float_as_uint(f);
    return (u & 0x80000000u) ? ~u : (u | 0x80000000u);
}
__device__ __forceinline__ float dec_f(unsigned k) {
    return __uint_as_float((k & 0x80000000u) ? (k ^ 0x80000000u) : ~k);
}

#define RITER ((NCAND + 1023) / 1024)

__global__ void k_readout(const int* __restrict__ cand,
                          const int* __restrict__ batch,
                          float* __restrict__ out) {
    __shared__ unsigned smx[GG];
    __shared__ float ssum[GG];
    int tid = threadIdx.x;
    for (int i = tid; i < GG; i += 1024) { smx[i] = 0u; ssum[i] = 0.f; }
    __syncthreads();
    float lg[RITER];
    int sg[RITER];
#pragma unroll
    for (int k = 0; k < RITER; k++) {
        int c = k * 1024 + tid;
        if (c < NCAND) {
            int n = cand[c];
            lg[k] = g_nl[n];
            sg[k] = batch[n];
            atomicMax(&smx[sg[k]], enc_f(lg[k]));
        }
    }
    __syncthreads();
#pragma unroll
    for (int k = 0; k < RITER; k++) {
        int c = k * 1024 + tid;
        if (c < NCAND) {
            lg[k] -= dec_f(smx[sg[k]]);
            atomicAdd(&ssum[sg[k]], expf(lg[k]));
        }
    }
    __syncthreads();
#pragma unroll
    for (int k = 0; k < RITER; k++) {
        int c = k * 1024 + tid;
        if (c < NCAND) out[c] = lg[k] - logf(ssum[sg[k]]);
    }
}

extern "C" void kernel_launch(void* const* d_in, const int* in_sizes, int n_in,
                              void* d_out, int out_size) {
    const float* x         = (const float*)d_in[0];
    const float* edge_attr = (const float*)d_in[1];
    const float* Wn_in     = (const float*)d_in[2];
    const float* bn_in     = (const float*)d_in[3];
    const float* We_in     = (const float*)d_in[4];
    const float* be_in     = (const float*)d_in[5];
    const float* We_l      = (const float*)d_in[6];
    const float* be_l      = (const float*)d_in[7];
    const float* Wn_l      = (const float*)d_in[8];
    const float* bn_l      = (const float*)d_in[9];
    const float* Wout      = (const float*)d_in[10];
    const float* bout      = (const float*)d_in[11];
    const int* edge_index  = (const int*)d_in[12];
    const int* batch       = (const int*)d_in[13];
    const int* cand        = (const int*)d_in[14];
    float* out = (float*)d_out;

    k_init<<<(TOT + 255) / 256, 256>>>(x, Wn_in, bn_in, We_l, be_l);
    for (int l = 0; l < LL; l++) {
        k_edge<<<(EE + 255) / 256, 256>>>(edge_index, edge_attr, We_l, We_in, be_in, l);
        k_node<<<(NN * 32 + 255) / 256, 256>>>(Wn_l, bn_l, We_l, be_l, Wout, bout, l);
    }
    k_readout<<<1, 1024>>>(cand, batch, out);
}

// round 6
// speedup vs baseline: 1.5251x; 1.0685x over previous
#include <cuda_runtime.h>
#include <cuda_fp16.h>
#include <math.h>

#define NN 100000
#define EE 1600000
#define NCAND 10000
#define GG 1000
#define ND 32
#define ED 8
#define LL 4

#define NBLK 444
#define NTHR 512
#define NT (NBLK * NTHR)          // 227328 threads
#define NWARP (NBLK * (NTHR / 32))

__device__ float g_h[NN * ND];                        // 12.8 MB fp32
__device__ __align__(16) __half g_hs[NN * ED];        // 1.6 MB fp16
__device__ __align__(16) __half g_hd[NN * ED];        // 1.6 MB fp16
__device__ __align__(16) float  g_agg[NN * ED];       // 3.2 MB fp32
__device__ __align__(16) __half g_e[(size_t)EE * ED]; // 25.6 MB fp16
__device__ float    g_nl[NN];                         // per-node logits
__device__ unsigned g_mxu[GG];
__device__ float    g_sum[GG];

// ---------------- grid barrier (all NBLK blocks co-resident) ----------------
__device__ unsigned g_cnt;
__device__ unsigned g_gen;

__device__ __forceinline__ void gbar() {
    __syncthreads();
    if (threadIdx.x == 0) {
        __threadfence();                       // release my block's writes
        unsigned gen = atomicAdd(&g_gen, 0u);  // read generation BEFORE arrival
        __threadfence();
        unsigned t = atomicAdd(&g_cnt, 1u);
        if (t == NBLK - 1) {
            *(volatile unsigned*)&g_cnt = 0u;
            __threadfence();
            atomicAdd(&g_gen, 1u);
        } else {
            while (*(volatile unsigned*)&g_gen == gen) { }
        }
        __threadfence();                       // acquire (CCTL.IVALL: drop stale L1)
    }
    __syncthreads();
}

// ---------------- helpers ----------------
__device__ __forceinline__ unsigned enc_f(float f) {
    unsigned u = __float_as_uint(f);
    return (u & 0x80000000u) ? ~u : (u | 0x80000000u);
}
__device__ __forceinline__ float dec_f(unsigned k) {
    return __uint_as_float((k & 0x80000000u) ? (k ^ 0x80000000u) : ~k);
}

#define R_A (NN * ND)            // h
#define R_B (R_A + NN * 16)      // hs/hd layer 0
#define R_C (R_B + NN * ED)      // agg zero
#define R_D (R_C + GG)           // mx
#define R_E (R_D + GG)           // sum
#define TOT R_E

// ---------------- phases ----------------
__device__ __forceinline__ void init_phase(int gtid, float* SM,
        const float* x, const float* Wn, const float* bn,
        const float* Wel, const float* bel) {
    float* sC = SM;        // [2][16]
    float* sc0 = SM + 32;  // [16]
    int tid = threadIdx.x;
    if (tid < 48) {
        int r = tid >> 4, j = tid & 15;
        float acc = 0.f;
        if (r < 2) {
            for (int i = 0; i < ND; i++) {
                float w = (j < 8) ? Wel[i * ED + j] : Wel[(ND + i) * ED + (j - 8)];
                acc = fmaf(Wn[r * ND + i], w, acc);
            }
            sC[r * 16 + j] = acc;
        } else {
            for (int i = 0; i < ND; i++) {
                float w = (j < 8) ? Wel[i * ED + j] : Wel[(ND + i) * ED + (j - 8)];
                acc = fmaf(bn[i], w, acc);
            }
            sc0[j] = acc + ((j < 8) ? bel[j] : 0.f);
        }
    }
    __syncthreads();
    for (long t = gtid; t < TOT; t += NT) {
        if (t < R_A) {
            int n = (int)(t >> 5), c = (int)(t & 31);
            g_h[t] = fmaf(x[2 * n], Wn[c], fmaf(x[2 * n + 1], Wn[ND + c], bn[c]));
        } else if (t < R_B) {
            long u = t - R_A;
            int n = (int)(u >> 4), j = (int)(u & 15);
            float v = fmaf(x[2 * n], sC[j], fmaf(x[2 * n + 1], sC[16 + j], sc0[j]));
            if (j < 8) g_hs[n * ED + j] = __float2half(v);
            else       g_hd[n * ED + (j - 8)] = __float2half(v);
        } else if (t < R_C) {
            g_agg[t - R_B] = 0.f;
        } else if (t < R_D) {
            g_mxu[t - R_C] = 0u;          // == enc(-inf) lower bound
        } else {
            g_sum[t - R_D] = 0.f;
        }
    }
}

__device__ __forceinline__ void edge_phase(int gtid, float* SM,
        const int* ei, const float* ea, const float* Wel,
        const float* Wei, const float* bei, int l) {
    float* sW = SM;         // 64
    float* sWei = SM + 64;  // 8
    float* sbei = SM + 72;  // 8
    if (threadIdx.x < 64)
        sW[threadIdx.x] = Wel[l * (2 * ND + ED) * ED + 2 * ND * ED + threadIdx.x];
    if (l == 0 && threadIdx.x >= 64 && threadIdx.x < 80) {
        int j = threadIdx.x - 64;
        if (j < 8) sWei[j] = Wei[j];
        else       sbei[j - 8] = bei[j - 8];
    }
    __syncthreads();
    for (int e = gtid; e < EE; e += NT) {
        int src = ei[e], dst = ei[EE + e];
        float ein[8];
        if (l == 0) {
            float v = ea[e];
#pragma unroll
            for (int j = 0; j < 8; j++) ein[j] = fmaf(v, sWei[j], sbei[j]);
        } else {
            uint4 ev = *(const uint4*)&g_e[(size_t)e * ED];
            const __half2* eh = (const __half2*)&ev;
#pragma unroll
            for (int k = 0; k < 4; k++) {
                float2 ef = __half22float2(eh[k]);
                ein[2 * k] = ef.x;
                ein[2 * k + 1] = ef.y;
            }
        }
        uint4 sv = *(const uint4*)&g_hs[(size_t)src * ED];
        uint4 dv = *(const uint4*)&g_hd[(size_t)dst * ED];
        const __half2* sh = (const __half2*)&sv;
        const __half2* dh = (const __half2*)&dv;
        float base[8];
#pragma unroll
        for (int k = 0; k < 4; k++) {
            float2 sf = __half22float2(sh[k]);
            float2 df = __half22float2(dh[k]);
            base[2 * k] = sf.x + df.x;
            base[2 * k + 1] = sf.y + df.y;
        }
        float ne[8];
#pragma unroll
        for (int j = 0; j < 8; j++) {
            float acc = base[j];
#pragma unroll
            for (int i = 0; i < 8; i++) acc = fmaf(ein[i], sW[i * ED + j], acc);
            ne[j] = fmaxf(acc, 0.f);
        }
        float* ap = &g_agg[(size_t)dst * ED];
        asm volatile("red.global.add.v4.f32 [%0], {%1,%2,%3,%4};"
                     :: "l"(ap), "f"(ne[0]), "f"(ne[1]), "f"(ne[2]), "f"(ne[3]) : "memory");
        asm volatile("red.global.add.v4.f32 [%0], {%1,%2,%3,%4};"
                     :: "l"(ap + 4), "f"(ne[4]), "f"(ne[5]), "f"(ne[6]), "f"(ne[7]) : "memory");
        if (l < LL - 1) {
            __half2 o[4];
#pragma unroll
            for (int k = 0; k < 4; k++)
                o[k] = __floats2half2_rn(ein[2 * k] + ne[2 * k],
                                         ein[2 * k + 1] + ne[2 * k + 1]);
            ((uint4*)&g_e[(size_t)e * ED])[0] = *(uint4*)o;
        }
    }
}

__device__ __forceinline__ void node_phase(int gtid, float* SM,
        const float* Wnl, const float* bnl, const float* Wel, const float* bel,
        const float* Wout, const float* bout, int l) {
    float* sW = SM;           // 1280
    float* sb = SM + 1280;    // 32
    float* sE = SM + 1312;    // 512 (32x16)
    float* sbe = SM + 1824;   // 8
    float* sWo = SM + 1832;   // 32
    float* sbo = SM + 1864;   // 1
    const int last = (l == LL - 1);
    for (int i = threadIdx.x; i < (ND + ED) * ND; i += NTHR)
        sW[i] = Wnl[l * (ND + ED) * ND + i];
    if (threadIdx.x < ND) sb[threadIdx.x] = bnl[l * ND + threadIdx.x];
    if (!last) {
        const float* W = Wel + (l + 1) * (2 * ND + ED) * ED;
        for (int i = threadIdx.x; i < ND * 16; i += NTHR) {
            int r = i >> 4, j = i & 15;
            sE[i] = (j < 8) ? W[r * ED + j] : W[(ND + r) * ED + (j - 8)];
        }
        if (threadIdx.x < 8) sbe[threadIdx.x] = bel[(l + 1) * ED + threadIdx.x];
    } else {
        if (threadIdx.x < ND) sWo[threadIdx.x] = Wout[threadIdx.x];
        if (threadIdx.x == 0) sbo[0] = bout[0];
    }
    __syncthreads();
    int lane = threadIdx.x & 31;
    for (int n = gtid >> 5; n < NN; n += NWARP) {
        float hv = g_h[n * ND + lane];
        float av = (lane < ED) ? g_agg[n * ED + lane] : 0.f;
        float r = sb[lane];
#pragma unroll
        for (int i = 0; i < ND; i++)
            r = fmaf(__shfl_sync(0xffffffffu, hv, i), sW[i * ND + lane], r);
#pragma unroll
        for (int i = 0; i < ED; i++)
            r = fmaf(__shfl_sync(0xffffffffu, av, i), sW[(ND + i) * ND + lane], r);
        float hnew = hv + fmaxf(r, 0.f);
        if (!last) {
            g_h[n * ND + lane] = hnew;
            float acc = (lane < 8) ? sbe[lane] : 0.f;
            int jj = lane & 15;
#pragma unroll
            for (int i = 0; i < ND; i++)
                acc = fmaf(__shfl_sync(0xffffffffu, hnew, i), sE[i * 16 + jj], acc);
            if (lane < 8) {
                g_hs[n * ED + lane] = __float2half(acc);
                g_agg[n * ED + lane] = 0.f;
            } else if (lane < 16) {
                g_hd[n * ED + (lane - 8)] = __float2half(acc);
            }
        } else {
            float p = hnew * sWo[lane];
#pragma unroll
            for (int s = 16; s > 0; s >>= 1)
                p += __shfl_xor_sync(0xffffffffu, p, s);
            if (lane == 0) g_nl[n] = p + sbo[0];
        }
    }
}

// ---------------- mega kernel ----------------
__global__ void __launch_bounds__(NTHR, 3)
k_mega(const float* __restrict__ x,
       const float* __restrict__ ea,
       const float* __restrict__ Wn_in, const float* __restrict__ bn_in,
       const float* __restrict__ We_in, const float* __restrict__ be_in,
       const float* __restrict__ We_l,  const float* __restrict__ be_l,
       const float* __restrict__ Wn_l,  const float* __restrict__ bn_l,
       const float* __restrict__ Wout,  const float* __restrict__ bout,
       const int* __restrict__ ei,      const int* __restrict__ batch,
       const int* __restrict__ cand,    float* __restrict__ out) {
    __shared__ float SM[2048];
    int gtid = blockIdx.x * NTHR + threadIdx.x;

    init_phase(gtid, SM, x, Wn_in, bn_in, We_l, be_l);
    gbar();
    for (int l = 0; l < LL; l++) {
        edge_phase(gtid, SM, ei, ea, We_l, We_in, be_in, l);
        gbar();
        node_phase(gtid, SM, Wn_l, bn_l, We_l, be_l, Wout, bout, l);
        gbar();
    }
    // readout phase A: per-graph max
    for (int c = gtid; c < NCAND; c += NT) {
        int n = cand[c];
        atomicMax(&g_mxu[batch[n]], enc_f(g_nl[n]));
    }
    gbar();
    // phase B: sum of exp
    for (int c = gtid; c < NCAND; c += NT) {
        int n = cand[c];
        int s = batch[n];
        atomicAdd(&g_sum[s], expf(g_nl[n] - dec_f(g_mxu[s])));
    }
    gbar();
    // phase C: write output
    for (int c = gtid; c < NCAND; c += NT) {
        int n = cand[c];
        int s = batch[n];
        out[c] = g_nl[n] - dec_f(g_mxu[s]) - logf(g_sum[s]);
    }
}

extern "C" void kernel_launch(void* const* d_in, const int* in_sizes, int n_in,
                              void* d_out, int out_size) {
    const float* x         = (const float*)d_in[0];
    const float* edge_attr = (const float*)d_in[1];
    const float* Wn_in     = (const float*)d_in[2];
    const float* bn_in     = (const float*)d_in[3];
    const float* We_in     = (const float*)d_in[4];
    const float* be_in     = (const float*)d_in[5];
    const float* We_l      = (const float*)d_in[6];
    const float* be_l      = (const float*)d_in[7];
    const float* Wn_l      = (const float*)d_in[8];
    const float* bn_l      = (const float*)d_in[9];
    const float* Wout      = (const float*)d_in[10];
    const float* bout      = (const float*)d_in[11];
    const int* edge_index  = (const int*)d_in[12];
    const int* batch       = (const int*)d_in[13];
    const int* cand        = (const int*)d_in[14];
    float* out = (float*)d_out;

    k_mega<<<NBLK, NTHR>>>(x, edge_attr, Wn_in, bn_in, We_in, be_in,
                           We_l, be_l, Wn_l, bn_l, Wout, bout,
                           edge_index, batch, cand, out);
}